// round 2
// baseline (speedup 1.0000x reference)
#include <cuda_runtime.h>
#include <math.h>

#define DEG2RAD 0.017453292519943295f
#define CLIP1(v) fminf(fmaxf((v), -1.0f + 1e-5f), 1.0f - 1e-5f)

__device__ __forceinline__ float4 ld4(const float* p) {
    return *reinterpret_cast<const float4*>(p);
}
__device__ __forceinline__ void fma4(float4& r, float v, const float4& w) {
    r.x = fmaf(v, w.x, r.x);
    r.y = fmaf(v, w.y, r.y);
    r.z = fmaf(v, w.z, r.z);
    r.w = fmaf(v, w.w, r.w);
}

// Output layout per face row (1056 floats):
// [0,576)    e_coor      dot9(face_coords, Wc)
// [576,624)  e_angle     dot3(angles, Wa)
// [624,816)  e_normal    dot3(normals, Wn)
// [816,832)  e_area      area * Warea
// [832,1024) e_emangle   CONSTANT per batch (folded into base)
// [1024,1040) e_emnoangle emno * Wemno
// [1040,1056) e_emfreq    CONSTANT per batch (folded into base)

__global__ __launch_bounds__(256) void meshcodec_kernel(
    const float* __restrict__ vertices, const int* __restrict__ faces,
    const float* __restrict__ theta, const float* __restrict__ phi,
    const float* __restrict__ freq,
    const float* __restrict__ W_angle,     const float* __restrict__ b_angle,
    const float* __restrict__ W_area,      const float* __restrict__ b_area,
    const float* __restrict__ W_normal,    const float* __restrict__ b_normal,
    const float* __restrict__ W_emnoangle, const float* __restrict__ b_emnoangle,
    const float* __restrict__ W_emangle,   const float* __restrict__ b_emangle,
    const float* __restrict__ W_emfreq,    const float* __restrict__ b_emfreq,
    const float* __restrict__ W_coor,      const float* __restrict__ b_coor,
    float* __restrict__ out, int V, int F)
{
    __shared__ float feat[256][20];   // per-face: 9 coords, 3 angles, 3 normal, area, emnoangle

    const int t     = threadIdx.x;
    const int bi    = blockIdx.y;
    const int face0 = blockIdx.x * 256;
    const int c0    = t * 4;

    // ---- per-batch scalars ----
    const float th = theta[bi] * DEG2RAD;
    const float ph = phi[bi]   * DEG2RAD;
    float sph, cph, sth, cth;
    sincosf(ph, &sph, &cph);
    sincosf(th, &sth, &cth);
    const float incx = sph * cth, incy = sph * sth, incz = cph;
    const float inorm = sqrtf(incx*incx + incy*incy + incz*incz);
    const float iinv  = 1.0f / fmaxf(inorm, 1e-12f);
    const float inx = incx*iinv, iny = incy*iinv, inz = incz*iinv;
    const float freq_log = (log10f(freq[bi]) + 1.0f) * 0.5f;

    // ---- per-thread weight columns (registers) ----
    float4 w[9];
    float4 base;
    int seg;
    if (c0 < 576) {                        // e_coor
        seg = 0;
        #pragma unroll
        for (int k = 0; k < 9; k++) w[k] = ld4(W_coor + k * 576 + c0);
        base = ld4(b_coor + c0);
    } else if (c0 < 624) {                 // e_angle
        seg = 1;
        const int l = c0 - 576;
        #pragma unroll
        for (int k = 0; k < 3; k++) w[k] = ld4(W_angle + k * 48 + l);
        base = ld4(b_angle + l);
    } else if (c0 < 816) {                 // e_normal
        seg = 2;
        const int l = c0 - 624;
        #pragma unroll
        for (int k = 0; k < 3; k++) w[k] = ld4(W_normal + k * 192 + l);
        base = ld4(b_normal + l);
    } else if (c0 < 832) {                 // e_area
        seg = 3;
        const int l = c0 - 816;
        w[0] = ld4(W_area + l);
        base = ld4(b_area + l);
    } else {                               // e_emangle: constant per batch
        seg = 4;
        const int l = c0 - 832;
        const float4 w0 = ld4(W_emangle + l);
        const float4 w1 = ld4(W_emangle + 192 + l);
        const float4 w2 = ld4(W_emangle + 384 + l);
        base = ld4(b_emangle + l);
        base.x += incx*w0.x + incy*w1.x + incz*w2.x;
        base.y += incx*w0.y + incy*w1.y + incz*w2.y;
        base.z += incx*w0.z + incy*w1.z + incz*w2.z;
        base.w += incx*w0.w + incy*w1.w + incz*w2.w;
    }

    // secondary column group: threads 0..7 also own cols [1024,1056)
    float4 w2nd = make_float4(0.f, 0.f, 0.f, 0.f);
    float4 base2 = make_float4(0.f, 0.f, 0.f, 0.f);
    if (t < 4) {                           // e_emnoangle
        w2nd  = ld4(W_emnoangle + 4 * t);
        base2 = ld4(b_emnoangle + 4 * t);
    } else if (t < 8) {                    // e_emfreq: constant per batch
        const int l = 4 * (t - 4);
        const float4 wf = ld4(W_emfreq + l);
        base2 = ld4(b_emfreq + l);
        base2.x += freq_log * wf.x;
        base2.y += freq_log * wf.y;
        base2.z += freq_log * wf.z;
        base2.w += freq_log * wf.w;
    }

    // ---- phase 1: per-face features ----
    const long long fb = (long long)bi * F + face0;
    {
        const int f = face0 + t;
        if (f < F) {
            const int* fp = faces + (fb + t) * 3;
            const int i0 = fp[0], i1 = fp[1], i2 = fp[2];
            const float* vb = vertices + (long long)bi * V * 3;
            const float Ax = vb[3*i0], Ay = vb[3*i0+1], Az = vb[3*i0+2];
            const float Bx = vb[3*i1], By = vb[3*i1+1], Bz = vb[3*i1+2];
            const float Cx = vb[3*i2], Cy = vb[3*i2+1], Cz = vb[3*i2+2];

            // edges: e0 = A-C, e1 = B-A, e2 = C-B
            const float e0x = Ax-Cx, e0y = Ay-Cy, e0z = Az-Cz;
            const float e1x = Bx-Ax, e1y = By-Ay, e1z = Bz-Az;
            const float e2x = Cx-Bx, e2y = Cy-By, e2z = Cz-Bz;

            const float r0 = 1.0f / fmaxf(sqrtf(e0x*e0x + e0y*e0y + e0z*e0z), 1e-12f);
            const float r1 = 1.0f / fmaxf(sqrtf(e1x*e1x + e1y*e1y + e1z*e1z), 1e-12f);
            const float r2 = 1.0f / fmaxf(sqrtf(e2x*e2x + e2y*e2y + e2z*e2z), 1e-12f);
            const float n0x = e0x*r0, n0y = e0y*r0, n0z = e0z*r0;
            const float n1x = e1x*r1, n1y = e1y*r1, n1z = e1z*r1;
            const float n2x = e2x*r2, n2y = e2y*r2, n2z = e2z*r2;

            // nd[c] = -sum_v nv[v,c]*nv[v,(c+2)%3]  (roll along coord axis, sum over vertices)
            const float nd0 = -(n0x*n0z + n1x*n1z + n2x*n2z);
            const float nd1 = -(n0y*n0x + n1y*n1x + n2y*n2x);
            const float nd2 = -(n0z*n0y + n1z*n1y + n2z*n2y);
            const float a0 = acosf(CLIP1(nd0));
            const float a1 = acosf(CLIP1(nd1));
            const float a2 = acosf(CLIP1(nd2));

            // cross(e0, e1)
            const float crx = e0y*e1z - e0z*e1y;
            const float cry = e0z*e1x - e0x*e1z;
            const float crz = e0x*e1y - e0y*e1x;
            const float cn = sqrtf(crx*crx + cry*cry + crz*crz);
            const float ci = 1.0f / fmaxf(cn, 1e-12f);
            const float nx = crx*ci, ny = cry*ci, nz = crz*ci;
            const float area = 0.5f * cn;

            const float emno = acosf(CLIP1(-(nx*inx + ny*iny + nz*inz)));

            float* fr = feat[t];
            fr[0] = Ax; fr[1] = Ay; fr[2] = Az;
            fr[3] = Bx; fr[4] = By; fr[5] = Bz;
            fr[6] = Cx; fr[7] = Cy; fr[8] = Cz;
            fr[9] = a0; fr[10] = a1; fr[11] = a2;
            fr[12] = nx; fr[13] = ny; fr[14] = nz;
            fr[15] = area; fr[16] = emno;
        }
    }
    __syncthreads();

    // ---- phase 2: write outputs ----
    const int nf = min(256, F - face0);
    float* outbase = out + fb * 1056 + c0;
    float* out2base = out + fb * 1056 + 1024 + 4 * t;   // only used when t<8

    #pragma unroll 2
    for (int f = 0; f < nf; f++) {
        const float* ftp = feat[f];
        float4 r = base;
        if (seg == 0) {
            const float4 p0 = *reinterpret_cast<const float4*>(ftp);
            const float4 p1 = *reinterpret_cast<const float4*>(ftp + 4);
            const float p8 = ftp[8];
            fma4(r, p0.x, w[0]); fma4(r, p0.y, w[1]); fma4(r, p0.z, w[2]);
            fma4(r, p0.w, w[3]); fma4(r, p1.x, w[4]); fma4(r, p1.y, w[5]);
            fma4(r, p1.z, w[6]); fma4(r, p1.w, w[7]); fma4(r, p8,   w[8]);
        } else if (seg == 1) {
            fma4(r, ftp[9],  w[0]); fma4(r, ftp[10], w[1]); fma4(r, ftp[11], w[2]);
        } else if (seg == 2) {
            fma4(r, ftp[12], w[0]); fma4(r, ftp[13], w[1]); fma4(r, ftp[14], w[2]);
        } else if (seg == 3) {
            fma4(r, ftp[15], w[0]);
        }
        // seg == 4: constant, r == base
        *reinterpret_cast<float4*>(outbase + (long long)f * 1056) = r;

        if (t < 8) {
            float4 r2 = base2;
            if (t < 4) fma4(r2, ftp[16], w2nd);
            *reinterpret_cast<float4*>(out2base + (long long)f * 1056) = r2;
        }
    }
}

extern "C" void kernel_launch(void* const* d_in, const int* in_sizes, int n_in,
                              void* d_out, int out_size) {
    const float* vertices     = (const float*)d_in[0];
    const int*   faces        = (const int*)  d_in[1];
    const float* theta        = (const float*)d_in[2];
    const float* phi          = (const float*)d_in[3];
    const float* freq         = (const float*)d_in[4];
    const float* W_angle      = (const float*)d_in[5];
    const float* b_angle      = (const float*)d_in[6];
    const float* W_area       = (const float*)d_in[7];
    const float* b_area       = (const float*)d_in[8];
    const float* W_normal     = (const float*)d_in[9];
    const float* b_normal     = (const float*)d_in[10];
    const float* W_emnoangle  = (const float*)d_in[11];
    const float* b_emnoangle  = (const float*)d_in[12];
    const float* W_emangle    = (const float*)d_in[13];
    const float* b_emangle    = (const float*)d_in[14];
    const float* W_emfreq     = (const float*)d_in[15];
    const float* b_emfreq     = (const float*)d_in[16];
    const float* W_coor       = (const float*)d_in[17];
    const float* b_coor       = (const float*)d_in[18];
    float* out = (float*)d_out;

    const int B = in_sizes[2];                 // theta has B elements
    const int F = in_sizes[1] / (3 * B);       // faces: B*F*3
    const int V = in_sizes[0] / (3 * B);       // vertices: B*V*3

    dim3 grid((F + 255) / 256, B);
    meshcodec_kernel<<<grid, 256>>>(
        vertices, faces, theta, phi, freq,
        W_angle, b_angle, W_area, b_area, W_normal, b_normal,
        W_emnoangle, b_emnoangle, W_emangle, b_emangle,
        W_emfreq, b_emfreq, W_coor, b_coor,
        out, V, F);
}

// round 7
// speedup vs baseline: 1.4413x; 1.4413x over previous
#include <cuda_runtime.h>
#include <math.h>

#define DEG2RAD 0.017453292519943295f
#define CLIP1(v) fminf(fmaxf((v), -1.0f + 1e-5f), 1.0f - 1e-5f)
#define FPB 128   // faces per block

__device__ __forceinline__ float4 ld4(const float* p) {
    return *reinterpret_cast<const float4*>(p);
}
__device__ __forceinline__ void fma4(float4& r, float v, const float4& w) {
    r.x = fmaf(v, w.x, r.x);
    r.y = fmaf(v, w.y, r.y);
    r.z = fmaf(v, w.z, r.z);
    r.w = fmaf(v, w.w, r.w);
}

// Output row (1056 floats):
// [0,576)=coor dot9 | [576,624)=angle dot3 | [624,816)=normal dot3 | [816,832)=area dot1
// [832,1024)=emangle CONST | [1024,1040)=emnoangle dot1 | [1040,1056)=emfreq CONST
// Threads 0..255 own cols 4t (0..1023). Warp-7 threads 224..231 also own cols 1024..1055
// (warp 7's primary segment is the constant emangle block, so it has spare issue slots).

__global__ __launch_bounds__(256, 4) void meshcodec_kernel(
    const float* __restrict__ vertices, const int* __restrict__ faces,
    const float* __restrict__ theta, const float* __restrict__ phi,
    const float* __restrict__ freq,
    const float* __restrict__ W_angle,     const float* __restrict__ b_angle,
    const float* __restrict__ W_area,      const float* __restrict__ b_area,
    const float* __restrict__ W_normal,    const float* __restrict__ b_normal,
    const float* __restrict__ W_emnoangle, const float* __restrict__ b_emnoangle,
    const float* __restrict__ W_emangle,   const float* __restrict__ b_emangle,
    const float* __restrict__ W_emfreq,    const float* __restrict__ b_emfreq,
    const float* __restrict__ W_coor,      const float* __restrict__ b_coor,
    float* __restrict__ out, int V, int F)
{
    __shared__ float feat[FPB][20];

    const int t     = threadIdx.x;
    const int bi    = blockIdx.y;
    const int face0 = blockIdx.x * FPB;
    const int c0    = t * 4;

    // ---- per-batch scalars ----
    const float th = theta[bi] * DEG2RAD;
    const float ph = phi[bi]   * DEG2RAD;
    float sph, cph, sth, cth;
    sincosf(ph, &sph, &cph);
    sincosf(th, &sth, &cth);
    const float incx = sph * cth, incy = sph * sth, incz = cph;
    const float iinv  = 1.0f / fmaxf(sqrtf(incx*incx + incy*incy + incz*incz), 1e-12f);
    const float inx = incx*iinv, iny = incy*iinv, inz = incz*iinv;
    const float freq_log = (log10f(freq[bi]) + 1.0f) * 0.5f;

    // ---- phase 1: per-face features (threads 0..FPB-1) ----
    const long long fb = (long long)bi * F + face0;
    if (t < FPB && face0 + t < F) {
        const int* fp = faces + (fb + t) * 3;
        const int i0 = fp[0], i1 = fp[1], i2 = fp[2];
        const float* vb = vertices + (long long)bi * V * 3;
        const float Ax = vb[3*i0], Ay = vb[3*i0+1], Az = vb[3*i0+2];
        const float Bx = vb[3*i1], By = vb[3*i1+1], Bz = vb[3*i1+2];
        const float Cx = vb[3*i2], Cy = vb[3*i2+1], Cz = vb[3*i2+2];

        const float e0x = Ax-Cx, e0y = Ay-Cy, e0z = Az-Cz;
        const float e1x = Bx-Ax, e1y = By-Ay, e1z = Bz-Az;
        const float e2x = Cx-Bx, e2y = Cy-By, e2z = Cz-Bz;

        const float r0 = 1.0f / fmaxf(sqrtf(e0x*e0x + e0y*e0y + e0z*e0z), 1e-12f);
        const float r1 = 1.0f / fmaxf(sqrtf(e1x*e1x + e1y*e1y + e1z*e1z), 1e-12f);
        const float r2 = 1.0f / fmaxf(sqrtf(e2x*e2x + e2y*e2y + e2z*e2z), 1e-12f);
        const float n0x = e0x*r0, n0y = e0y*r0, n0z = e0z*r0;
        const float n1x = e1x*r1, n1y = e1y*r1, n1z = e1z*r1;
        const float n2x = e2x*r2, n2y = e2y*r2, n2z = e2z*r2;

        const float nd0 = -(n0x*n0z + n1x*n1z + n2x*n2z);
        const float nd1 = -(n0y*n0x + n1y*n1x + n2y*n2x);
        const float nd2 = -(n0z*n0y + n1z*n1y + n2z*n2y);
        const float a0 = acosf(CLIP1(nd0));
        const float a1 = acosf(CLIP1(nd1));
        const float a2 = acosf(CLIP1(nd2));

        const float crx = e0y*e1z - e0z*e1y;
        const float cry = e0z*e1x - e0x*e1z;
        const float crz = e0x*e1y - e0y*e1x;
        const float cn = sqrtf(crx*crx + cry*cry + crz*crz);
        const float ci = 1.0f / fmaxf(cn, 1e-12f);
        const float nx = crx*ci, ny = cry*ci, nz = crz*ci;
        const float area = 0.5f * cn;
        const float emno = acosf(CLIP1(-(nx*inx + ny*iny + nz*inz)));

        float* fr = feat[t];
        fr[0] = Ax; fr[1] = Ay; fr[2] = Az;
        fr[3] = Bx; fr[4] = By; fr[5] = Bz;
        fr[6] = Cx; fr[7] = Cy; fr[8] = Cz;
        fr[9] = a0; fr[10] = a1; fr[11] = a2;
        fr[12] = nx; fr[13] = ny; fr[14] = nz;
        fr[15] = area; fr[16] = emno;
    }
    __syncthreads();

    // ---- phase 2: per-segment specialized loops ----
    const int nf = min(FPB, F - face0);
    float* op = out + fb * 1056 + c0;

    if (c0 < 576) {                                   // ---- e_coor: dot9 ----
        float4 w0 = ld4(W_coor + 0*576 + c0), w1 = ld4(W_coor + 1*576 + c0);
        float4 w2 = ld4(W_coor + 2*576 + c0), w3 = ld4(W_coor + 3*576 + c0);
        float4 w4 = ld4(W_coor + 4*576 + c0), w5 = ld4(W_coor + 5*576 + c0);
        float4 w6 = ld4(W_coor + 6*576 + c0), w7 = ld4(W_coor + 7*576 + c0);
        float4 w8 = ld4(W_coor + 8*576 + c0);
        const float4 base = ld4(b_coor + c0);
        #pragma unroll 2
        for (int f = 0; f < nf; f++, op += 1056) {
            const float* ftp = feat[f];
            const float4 p0 = *reinterpret_cast<const float4*>(ftp);
            const float4 p1 = *reinterpret_cast<const float4*>(ftp + 4);
            const float p8 = ftp[8];
            float4 r = base;
            fma4(r, p0.x, w0); fma4(r, p0.y, w1); fma4(r, p0.z, w2);
            fma4(r, p0.w, w3); fma4(r, p1.x, w4); fma4(r, p1.y, w5);
            fma4(r, p1.z, w6); fma4(r, p1.w, w7); fma4(r, p8,   w8);
            *reinterpret_cast<float4*>(op) = r;
        }
    } else if (c0 < 624) {                            // ---- e_angle: dot3 ----
        const int l = c0 - 576;
        float4 w0 = ld4(W_angle + l), w1 = ld4(W_angle + 48 + l), w2 = ld4(W_angle + 96 + l);
        const float4 base = ld4(b_angle + l);
        #pragma unroll 4
        for (int f = 0; f < nf; f++, op += 1056) {
            const float* ftp = feat[f];
            float4 r = base;
            fma4(r, ftp[9], w0); fma4(r, ftp[10], w1); fma4(r, ftp[11], w2);
            *reinterpret_cast<float4*>(op) = r;
        }
    } else if (c0 < 816) {                            // ---- e_normal: dot3 ----
        const int l = c0 - 624;
        float4 w0 = ld4(W_normal + l), w1 = ld4(W_normal + 192 + l), w2 = ld4(W_normal + 384 + l);
        const float4 base = ld4(b_normal + l);
        #pragma unroll 4
        for (int f = 0; f < nf; f++, op += 1056) {
            const float* ftp = feat[f];
            float4 r = base;
            fma4(r, ftp[12], w0); fma4(r, ftp[13], w1); fma4(r, ftp[14], w2);
            *reinterpret_cast<float4*>(op) = r;
        }
    } else if (c0 < 832) {                            // ---- e_area: dot1 ----
        const int l = c0 - 816;
        float4 w0 = ld4(W_area + l);
        const float4 base = ld4(b_area + l);
        #pragma unroll 4
        for (int f = 0; f < nf; f++, op += 1056) {
            float4 r = base;
            fma4(r, feat[f][15], w0);
            *reinterpret_cast<float4*>(op) = r;
        }
    } else {                                          // ---- e_emangle: CONST, + extra cols ----
        const int l = c0 - 832;
        const float4 w0 = ld4(W_emangle + l);
        const float4 w1 = ld4(W_emangle + 192 + l);
        const float4 w2 = ld4(W_emangle + 384 + l);
        float4 base = ld4(b_emangle + l);
        base.x += incx*w0.x + incy*w1.x + incz*w2.x;
        base.y += incx*w0.y + incy*w1.y + incz*w2.y;
        base.z += incx*w0.z + incy*w1.z + incz*w2.z;
        base.w += incx*w0.w + incy*w1.w + incz*w2.w;

        // warp 7 threads 224..231 also own cols [1024,1056)
        const int e = t - 224;                        // 0..7 valid
        const bool has2 = (e >= 0 && e < 8);
        float4 w2nd = make_float4(0.f, 0.f, 0.f, 0.f);
        float4 base2 = make_float4(0.f, 0.f, 0.f, 0.f);
        bool dyn2 = false;
        float* op2 = out + fb * 1056 + 1024 + 4 * e;
        if (has2) {
            if (e < 4) {                              // e_emnoangle
                w2nd  = ld4(W_emnoangle + 4 * e);
                base2 = ld4(b_emnoangle + 4 * e);
                dyn2 = true;
            } else {                                  // e_emfreq: const
                const int l2 = 4 * (e - 4);
                const float4 wf = ld4(W_emfreq + l2);
                base2 = ld4(b_emfreq + l2);
                base2.x += freq_log * wf.x;
                base2.y += freq_log * wf.y;
                base2.z += freq_log * wf.z;
                base2.w += freq_log * wf.w;
            }
        }
        #pragma unroll 4
        for (int f = 0; f < nf; f++, op += 1056, op2 += 1056) {
            *reinterpret_cast<float4*>(op) = base;
            if (has2) {
                float4 r2 = base2;
                if (dyn2) fma4(r2, feat[f][16], w2nd);
                *reinterpret_cast<float4*>(op2) = r2;
            }
        }
    }
}

extern "C" void kernel_launch(void* const* d_in, const int* in_sizes, int n_in,
                              void* d_out, int out_size) {
    const float* vertices     = (const float*)d_in[0];
    const int*   faces        = (const int*)  d_in[1];
    const float* theta        = (const float*)d_in[2];
    const float* phi          = (const float*)d_in[3];
    const float* freq         = (const float*)d_in[4];
    const float* W_angle      = (const float*)d_in[5];
    const float* b_angle      = (const float*)d_in[6];
    const float* W_area       = (const float*)d_in[7];
    const float* b_area       = (const float*)d_in[8];
    const float* W_normal     = (const float*)d_in[9];
    const float* b_normal     = (const float*)d_in[10];
    const float* W_emnoangle  = (const float*)d_in[11];
    const float* b_emnoangle  = (const float*)d_in[12];
    const float* W_emangle    = (const float*)d_in[13];
    const float* b_emangle    = (const float*)d_in[14];
    const float* W_emfreq     = (const float*)d_in[15];
    const float* b_emfreq     = (const float*)d_in[16];
    const float* W_coor       = (const float*)d_in[17];
    const float* b_coor       = (const float*)d_in[18];
    float* out = (float*)d_out;

    const int B = in_sizes[2];
    const int F = in_sizes[1] / (3 * B);
    const int V = in_sizes[0] / (3 * B);

    dim3 grid((F + FPB - 1) / FPB, B);
    meshcodec_kernel<<<grid, 256>>>(
        vertices, faces, theta, phi, freq,
        W_angle, b_angle, W_area, b_area, W_normal, b_normal,
        W_emnoangle, b_emnoangle, W_emangle, b_emangle,
        W_emfreq, b_emfreq, W_coor, b_coor,
        out, V, F);
}

// round 9
// speedup vs baseline: 1.7894x; 1.2415x over previous
#include <cuda_runtime.h>
#include <math.h>

#define DEG2RAD 0.017453292519943295f
#define CLIP1(v) fminf(fmaxf((v), -1.0f + 1e-5f), 1.0f - 1e-5f)
#define FPB 32   // faces per block: small tiles to smooth the tail ramp-down

__device__ __forceinline__ float4 ld4(const float* p) {
    return *reinterpret_cast<const float4*>(p);
}
__device__ __forceinline__ void fma4(float4& r, float v, const float4& w) {
    r.x = fmaf(v, w.x, r.x);
    r.y = fmaf(v, w.y, r.y);
    r.z = fmaf(v, w.z, r.z);
    r.w = fmaf(v, w.w, r.w);
}
__device__ __forceinline__ void st4s(float* p, const float4& r) {
    __stcs(reinterpret_cast<float4*>(p), r);   // streaming (evict-first) store
}

// Output row (1056 floats):
// [0,576)=coor dot9 | [576,624)=angle dot3 | [624,816)=normal dot3 | [816,832)=area dot1
// [832,1024)=emangle CONST | [1024,1040)=emnoangle dot1 | [1040,1056)=emfreq CONST
// Threads 0..255 own cols 4t (0..1023). Warp-7 threads 224..231 also own cols 1024..1055.

__global__ __launch_bounds__(256, 4) void meshcodec_kernel(
    const float* __restrict__ vertices, const int* __restrict__ faces,
    const float* __restrict__ theta, const float* __restrict__ phi,
    const float* __restrict__ freq,
    const float* __restrict__ W_angle,     const float* __restrict__ b_angle,
    const float* __restrict__ W_area,      const float* __restrict__ b_area,
    const float* __restrict__ W_normal,    const float* __restrict__ b_normal,
    const float* __restrict__ W_emnoangle, const float* __restrict__ b_emnoangle,
    const float* __restrict__ W_emangle,   const float* __restrict__ b_emangle,
    const float* __restrict__ W_emfreq,    const float* __restrict__ b_emfreq,
    const float* __restrict__ W_coor,      const float* __restrict__ b_coor,
    float* __restrict__ out, int V, int F)
{
    __shared__ float feat[FPB][20];

    const int t     = threadIdx.x;
    const int bi    = blockIdx.y;
    const int face0 = blockIdx.x * FPB;
    const int c0    = t * 4;

    // ---- per-batch scalars ----
    const float th = theta[bi] * DEG2RAD;
    const float ph = phi[bi]   * DEG2RAD;
    float sph, cph, sth, cth;
    sincosf(ph, &sph, &cph);
    sincosf(th, &sth, &cth);
    const float incx = sph * cth, incy = sph * sth, incz = cph;
    const float iinv  = 1.0f / fmaxf(sqrtf(incx*incx + incy*incy + incz*incz), 1e-12f);
    const float inx = incx*iinv, iny = incy*iinv, inz = incz*iinv;
    const float freq_log = (log10f(freq[bi]) + 1.0f) * 0.5f;

    // ---- phase 1: per-face features (threads 0..FPB-1) ----
    const long long fb = (long long)bi * F + face0;
    if (t < FPB && face0 + t < F) {
        const int* fp = faces + (fb + t) * 3;
        const int i0 = fp[0], i1 = fp[1], i2 = fp[2];
        const float* vb = vertices + (long long)bi * V * 3;
        const float Ax = vb[3*i0], Ay = vb[3*i0+1], Az = vb[3*i0+2];
        const float Bx = vb[3*i1], By = vb[3*i1+1], Bz = vb[3*i1+2];
        const float Cx = vb[3*i2], Cy = vb[3*i2+1], Cz = vb[3*i2+2];

        const float e0x = Ax-Cx, e0y = Ay-Cy, e0z = Az-Cz;
        const float e1x = Bx-Ax, e1y = By-Ay, e1z = Bz-Az;
        const float e2x = Cx-Bx, e2y = Cy-By, e2z = Cz-Bz;

        const float r0 = 1.0f / fmaxf(sqrtf(e0x*e0x + e0y*e0y + e0z*e0z), 1e-12f);
        const float r1 = 1.0f / fmaxf(sqrtf(e1x*e1x + e1y*e1y + e1z*e1z), 1e-12f);
        const float r2 = 1.0f / fmaxf(sqrtf(e2x*e2x + e2y*e2y + e2z*e2z), 1e-12f);
        const float n0x = e0x*r0, n0y = e0y*r0, n0z = e0z*r0;
        const float n1x = e1x*r1, n1y = e1y*r1, n1z = e1z*r1;
        const float n2x = e2x*r2, n2y = e2y*r2, n2z = e2z*r2;

        const float nd0 = -(n0x*n0z + n1x*n1z + n2x*n2z);
        const float nd1 = -(n0y*n0x + n1y*n1x + n2y*n2x);
        const float nd2 = -(n0z*n0y + n1z*n1y + n2z*n2y);
        const float a0 = acosf(CLIP1(nd0));
        const float a1 = acosf(CLIP1(nd1));
        const float a2 = acosf(CLIP1(nd2));

        const float crx = e0y*e1z - e0z*e1y;
        const float cry = e0z*e1x - e0x*e1z;
        const float crz = e0x*e1y - e0y*e1x;
        const float cn = sqrtf(crx*crx + cry*cry + crz*crz);
        const float ci = 1.0f / fmaxf(cn, 1e-12f);
        const float nx = crx*ci, ny = cry*ci, nz = crz*ci;
        const float area = 0.5f * cn;
        const float emno = acosf(CLIP1(-(nx*inx + ny*iny + nz*inz)));

        float* fr = feat[t];
        fr[0] = Ax; fr[1] = Ay; fr[2] = Az;
        fr[3] = Bx; fr[4] = By; fr[5] = Bz;
        fr[6] = Cx; fr[7] = Cy; fr[8] = Cz;
        fr[9] = a0; fr[10] = a1; fr[11] = a2;
        fr[12] = nx; fr[13] = ny; fr[14] = nz;
        fr[15] = area; fr[16] = emno;
    }
    __syncthreads();

    // ---- phase 2: per-segment specialized loops ----
    const int nf = min(FPB, F - face0);
    float* op = out + fb * 1056 + c0;

    if (c0 < 576) {                                   // ---- e_coor: dot9 ----
        float4 w0 = ld4(W_coor + 0*576 + c0), w1 = ld4(W_coor + 1*576 + c0);
        float4 w2 = ld4(W_coor + 2*576 + c0), w3 = ld4(W_coor + 3*576 + c0);
        float4 w4 = ld4(W_coor + 4*576 + c0), w5 = ld4(W_coor + 5*576 + c0);
        float4 w6 = ld4(W_coor + 6*576 + c0), w7 = ld4(W_coor + 7*576 + c0);
        float4 w8 = ld4(W_coor + 8*576 + c0);
        const float4 base = ld4(b_coor + c0);
        #pragma unroll 2
        for (int f = 0; f < nf; f++, op += 1056) {
            const float* ftp = feat[f];
            const float4 p0 = *reinterpret_cast<const float4*>(ftp);
            const float4 p1 = *reinterpret_cast<const float4*>(ftp + 4);
            const float p8 = ftp[8];
            float4 r = base;
            fma4(r, p0.x, w0); fma4(r, p0.y, w1); fma4(r, p0.z, w2);
            fma4(r, p0.w, w3); fma4(r, p1.x, w4); fma4(r, p1.y, w5);
            fma4(r, p1.z, w6); fma4(r, p1.w, w7); fma4(r, p8,   w8);
            st4s(op, r);
        }
    } else if (c0 < 624) {                            // ---- e_angle: dot3 ----
        const int l = c0 - 576;
        float4 w0 = ld4(W_angle + l), w1 = ld4(W_angle + 48 + l), w2 = ld4(W_angle + 96 + l);
        const float4 base = ld4(b_angle + l);
        #pragma unroll 4
        for (int f = 0; f < nf; f++, op += 1056) {
            const float* ftp = feat[f];
            float4 r = base;
            fma4(r, ftp[9], w0); fma4(r, ftp[10], w1); fma4(r, ftp[11], w2);
            st4s(op, r);
        }
    } else if (c0 < 816) {                            // ---- e_normal: dot3 ----
        const int l = c0 - 624;
        float4 w0 = ld4(W_normal + l), w1 = ld4(W_normal + 192 + l), w2 = ld4(W_normal + 384 + l);
        const float4 base = ld4(b_normal + l);
        #pragma unroll 4
        for (int f = 0; f < nf; f++, op += 1056) {
            const float* ftp = feat[f];
            float4 r = base;
            fma4(r, ftp[12], w0); fma4(r, ftp[13], w1); fma4(r, ftp[14], w2);
            st4s(op, r);
        }
    } else if (c0 < 832) {                            // ---- e_area: dot1 ----
        const int l = c0 - 816;
        float4 w0 = ld4(W_area + l);
        const float4 base = ld4(b_area + l);
        #pragma unroll 4
        for (int f = 0; f < nf; f++, op += 1056) {
            float4 r = base;
            fma4(r, feat[f][15], w0);
            st4s(op, r);
        }
    } else {                                          // ---- e_emangle: CONST, + extra cols ----
        const int l = c0 - 832;
        const float4 w0 = ld4(W_emangle + l);
        const float4 w1 = ld4(W_emangle + 192 + l);
        const float4 w2 = ld4(W_emangle + 384 + l);
        float4 base = ld4(b_emangle + l);
        base.x += incx*w0.x + incy*w1.x + incz*w2.x;
        base.y += incx*w0.y + incy*w1.y + incz*w2.y;
        base.z += incx*w0.z + incy*w1.z + incz*w2.z;
        base.w += incx*w0.w + incy*w1.w + incz*w2.w;

        // warp 7 threads 224..231 also own cols [1024,1056)
        const int e = t - 224;                        // 0..7 valid
        const bool has2 = (e >= 0 && e < 8);
        float4 w2nd = make_float4(0.f, 0.f, 0.f, 0.f);
        float4 base2 = make_float4(0.f, 0.f, 0.f, 0.f);
        bool dyn2 = false;
        float* op2 = out + fb * 1056 + 1024 + 4 * e;
        if (has2) {
            if (e < 4) {                              // e_emnoangle
                w2nd  = ld4(W_emnoangle + 4 * e);
                base2 = ld4(b_emnoangle + 4 * e);
                dyn2 = true;
            } else {                                  // e_emfreq: const
                const int l2 = 4 * (e - 4);
                const float4 wf = ld4(W_emfreq + l2);
                base2 = ld4(b_emfreq + l2);
                base2.x += freq_log * wf.x;
                base2.y += freq_log * wf.y;
                base2.z += freq_log * wf.z;
                base2.w += freq_log * wf.w;
            }
        }
        #pragma unroll 4
        for (int f = 0; f < nf; f++, op += 1056, op2 += 1056) {
            st4s(op, base);
            if (has2) {
                float4 r2 = base2;
                if (dyn2) fma4(r2, feat[f][16], w2nd);
                st4s(op2, r2);
            }
        }
    }
}

extern "C" void kernel_launch(void* const* d_in, const int* in_sizes, int n_in,
                              void* d_out, int out_size) {
    const float* vertices     = (const float*)d_in[0];
    const int*   faces        = (const int*)  d_in[1];
    const float* theta        = (const float*)d_in[2];
    const float* phi          = (const float*)d_in[3];
    const float* freq         = (const float*)d_in[4];
    const float* W_angle      = (const float*)d_in[5];
    const float* b_angle      = (const float*)d_in[6];
    const float* W_area       = (const float*)d_in[7];
    const float* b_area       = (const float*)d_in[8];
    const float* W_normal     = (const float*)d_in[9];
    const float* b_normal     = (const float*)d_in[10];
    const float* W_emnoangle  = (const float*)d_in[11];
    const float* b_emnoangle  = (const float*)d_in[12];
    const float* W_emangle    = (const float*)d_in[13];
    const float* b_emangle    = (const float*)d_in[14];
    const float* W_emfreq     = (const float*)d_in[15];
    const float* b_emfreq     = (const float*)d_in[16];
    const float* W_coor       = (const float*)d_in[17];
    const float* b_coor       = (const float*)d_in[18];
    float* out = (float*)d_out;

    const int B = in_sizes[2];
    const int F = in_sizes[1] / (3 * B);
    const int V = in_sizes[0] / (3 * B);

    dim3 grid((F + FPB - 1) / FPB, B);
    meshcodec_kernel<<<grid, 256>>>(
        vertices, faces, theta, phi, freq,
        W_angle, b_angle, W_area, b_area, W_normal, b_normal,
        W_emnoangle, b_emnoangle, W_emangle, b_emangle,
        W_emfreq, b_emfreq, W_coor, b_coor,
        out, V, F);
}